// round 1
// baseline (speedup 1.0000x reference)
#include <cuda_runtime.h>
#include <math.h>

// RoPE-2D: x[B=32, S=1024, H=16, D=64] fp32, grid_sizes[B,2] int32.
// Combined rotation: rot(i*theta) ∘ rot(j*theta) == rot((i+j)*theta).
// Cache {cos,sin}((i+j)*theta_k) for pos=i+j in [0,126], k in [0,32).

#define HALF 32
#define MAXPOS 127           // i+j <= 63+63 = 126
#define S_LOG2 10            // S = 1024
#define H_LOG2 4             // H = 16
#define F4_PER_ROW 16        // D=64 floats = 16 float4

// cache[pos][t] = {cos(pos*theta_{2t}), sin(pos*theta_{2t}), cos(pos*theta_{2t+1}), sin(pos*theta_{2t+1})}
__device__ float4 g_cache[MAXPOS * F4_PER_ROW];

__global__ void init_cache_kernel() {
    int idx = blockIdx.x * blockDim.x + threadIdx.x;   // one thread per (pos, pair k)
    if (idx >= MAXPOS * HALF) return;
    int pos = idx >> 5;          // / HALF
    int k   = idx & (HALF - 1);  // pair index 0..31
    // theta_k = 10000^(-k/32) = exp2(-k * log2(10000)/32)
    const float L2B_OVER_HALF = 13.287712379549449f / 32.0f;  // log2(10000)/32
    float theta = exp2f(-(float)k * L2B_OVER_HALF);
    float ang = (float)pos * theta;
    float s, c;
    sincosf(ang, &s, &c);        // accurate path; tiny kernel, cost irrelevant
    // interleave into float4 slots: two pairs per float4 slot
    float2* cache2 = reinterpret_cast<float2*>(g_cache);
    cache2[pos * HALF + k] = make_float2(c, s);
}

__global__ void rope2d_kernel(const float4* __restrict__ x,
                              const int* __restrict__ grid_sizes,
                              float4* __restrict__ out,
                              int total4) {
    int f = blockIdx.x * blockDim.x + threadIdx.x;
    if (f >= total4) return;

    int t = f & (F4_PER_ROW - 1);                  // which float4 within D (pairs 2t, 2t+1)
    int s = (f >> (H_LOG2 + 4)) & ((1 << S_LOG2) - 1);  // >>4 skips t, >>H_LOG2 skips h
    int b = f >> (S_LOG2 + H_LOG2 + 4);

    int cols = __ldg(&grid_sizes[2 * b + 1]);
    int i = s / cols;
    int j = s - i * cols;
    int pos = i + j;

    float4 cs = g_cache[pos * F4_PER_ROW + t];     // {c0, s0, c1, s1} — L1/L2 hit
    float4 v  = x[f];

    float4 o;
    o.x = fmaf(v.x, cs.x, -v.y * cs.y);
    o.y = fmaf(v.y, cs.x,  v.x * cs.y);
    o.z = fmaf(v.z, cs.z, -v.w * cs.w);
    o.w = fmaf(v.w, cs.z,  v.z * cs.w);

    out[f] = o;
}

extern "C" void kernel_launch(void* const* d_in, const int* in_sizes, int n_in,
                              void* d_out, int out_size) {
    const float4* x = (const float4*)d_in[0];
    const int* grid_sizes = (const int*)d_in[1];
    float4* out = (float4*)d_out;

    int total4 = in_sizes[0] / 4;   // 33,554,432 / 4 = 8,388,608 float4

    // Fill combined cos/sin cache (runs every replay; deterministic)
    init_cache_kernel<<<(MAXPOS * HALF + 255) / 256, 256>>>();

    rope2d_kernel<<<(total4 + 255) / 256, 256>>>(x, grid_sizes, out, total4);
}

// round 2
// speedup vs baseline: 1.0506x; 1.0506x over previous
#include <cuda_runtime.h>
#include <math.h>

// RoPE-2D: x[B=32, S=1024, H=16, D=64] fp32, grid_sizes[B,2] int32.
// Combined rotation: rot(i*theta) ∘ rot(j*theta) == rot((i+j)*theta).
// Precompute: {cos,sin}((i+j)*theta_k) table + per-(b,s) pos table.

#define HALF 32
#define MAXPOS 127           // i+j <= 63+63 = 126
#define NBS (32 * 1024)      // B * S
#define F4_PER_ROW 16        // D=64 floats = 16 float4

// cache[pos][t] = {cos, sin, cos, sin} for pairs 2t, 2t+1
__device__ float4 g_cache[MAXPOS * F4_PER_ROW];
// pos[b*1024 + s] = i + j
__device__ int g_pos[NBS];

__global__ void init_kernel(const int* __restrict__ grid_sizes) {
    int idx = blockIdx.x * blockDim.x + threadIdx.x;
    if (idx < NBS) {
        int b = idx >> 10;
        int s = idx & 1023;
        int cols = grid_sizes[2 * b + 1];
        int i = s / cols;
        int j = s - i * cols;
        g_pos[idx] = i + j;
    }
    if (idx < MAXPOS * HALF) {
        int pos = idx >> 5;
        int k = idx & (HALF - 1);
        const float L2B_OVER_HALF = 13.287712379549449f / 32.0f;  // log2(10000)/32
        float theta = exp2f(-(float)k * L2B_OVER_HALF);
        float sv, cv;
        sincosf((float)pos * theta, &sv, &cv);
        reinterpret_cast<float2*>(g_cache)[pos * HALF + k] = make_float2(cv, sv);
    }
}

// Block = 256 threads covers two (b,s) rows (512 float4). 2 float4/thread.
__global__ void __launch_bounds__(256) rope2d_kernel(const float4* __restrict__ x,
                                                     float4* __restrict__ out) {
    int tid = threadIdx.x;
    int row0 = blockIdx.x * 2;             // (b,s) index of first row
    long long base = (long long)blockIdx.x * 512 + tid;
    int f0 = (int)base;                    // element in row0 region
    int f1 = f0 + 256;                     // element in row1 region

    int t = tid & (F4_PER_ROW - 1);

    // broadcast loads, L1/L2-hit
    int pos0 = g_pos[row0];
    int pos1 = g_pos[row0 + 1];

    // issue both streaming x-loads back-to-back (MLP=2)
    float4 v0 = __ldcs(&x[f0]);
    float4 v1 = __ldcs(&x[f1]);

    float4 cs0 = g_cache[pos0 * F4_PER_ROW + t];
    float4 cs1 = g_cache[pos1 * F4_PER_ROW + t];

    float4 o0, o1;
    o0.x = fmaf(v0.x, cs0.x, -v0.y * cs0.y);
    o0.y = fmaf(v0.y, cs0.x,  v0.x * cs0.y);
    o0.z = fmaf(v0.z, cs0.z, -v0.w * cs0.w);
    o0.w = fmaf(v0.w, cs0.z,  v0.z * cs0.w);

    o1.x = fmaf(v1.x, cs1.x, -v1.y * cs1.y);
    o1.y = fmaf(v1.y, cs1.x,  v1.x * cs1.y);
    o1.z = fmaf(v1.z, cs1.z, -v1.w * cs1.w);
    o1.w = fmaf(v1.w, cs1.z,  v1.z * cs1.w);

    __stcs(&out[f0], o0);
    __stcs(&out[f1], o1);
}

extern "C" void kernel_launch(void* const* d_in, const int* in_sizes, int n_in,
                              void* d_out, int out_size) {
    const float4* x = (const float4*)d_in[0];
    const int* grid_sizes = (const int*)d_in[1];
    float4* out = (float4*)d_out;

    // 32768 threads: covers both pos table (32K) and cos/sin table (4064)
    init_kernel<<<NBS / 256, 256>>>(grid_sizes);

    int total4 = in_sizes[0] / 4;          // 8,388,608 float4
    int nblocks = total4 / 512;            // 16384 blocks, 2 float4/thread
    rope2d_kernel<<<nblocks, 256>>>(x, out);
}

// round 3
// speedup vs baseline: 1.0513x; 1.0007x over previous
#include <cuda_runtime.h>
#include <math.h>

// RoPE-2D: x[B=32, S=1024, H=16, D=64] fp32, grid_sizes[B,2] int32.
// Combined rotation: rot(i*theta) ∘ rot(j*theta) == rot((i+j)*theta).
// Single kernel: each block computes its own 4 rows' cos/sin into shared
// (128 fast sincos per block — amortized to noise), then streams x -> out.

#define F4_PER_ROW 16        // D=64 floats = 16 float4
#define ROWS_PER_BLK 4       // (b,s) rows per block
#define S_LOG2 10

__global__ void __launch_bounds__(256) rope2d_kernel(const float4* __restrict__ x,
                                                     const int* __restrict__ grid_sizes,
                                                     float4* __restrict__ out) {
    __shared__ float2 sh_cs[ROWS_PER_BLK * 32];   // [row][k] = {cos, sin}

    int tid = threadIdx.x;
    int row_base = blockIdx.x * ROWS_PER_BLK;
    long long fbase = (long long)blockIdx.x * (ROWS_PER_BLK * 256) + tid;
    int f0 = (int)fbase;

    // ---- issue all 4 streaming x-loads first (MLP=4, in flight during sincos) ----
    float4 v0 = __ldcs(&x[f0]);
    float4 v1 = __ldcs(&x[f0 + 256]);
    float4 v2 = __ldcs(&x[f0 + 512]);
    float4 v3 = __ldcs(&x[f0 + 768]);

    // ---- threads 0..127: compute cos/sin table for this block's 4 rows ----
    if (tid < ROWS_PER_BLK * 32) {
        int u = tid >> 5;                 // row within block
        int k = tid & 31;                 // pair index
        int row = row_base + u;
        int s = row & ((1 << S_LOG2) - 1);
        int b = row >> S_LOG2;
        int cols = __ldg(&grid_sizes[2 * b + 1]);
        int i = s / cols;
        int j = s - i * cols;
        float pos = (float)(i + j);
        const float L2B_OVER_HALF = 13.287712379549449f / 32.0f;  // log2(10000)/32
        float theta = exp2f(-(float)k * L2B_OVER_HALF);
        float sv, cv;
        __sincosf(pos * theta, &sv, &cv);
        sh_cs[tid] = make_float2(cv, sv);
    }
    __syncthreads();

    int t = tid & (F4_PER_ROW - 1);
    const float4* sh4 = reinterpret_cast<const float4*>(sh_cs);
    float4 cs0 = sh4[0 * F4_PER_ROW + t];    // {c_2t, s_2t, c_2t+1, s_2t+1}
    float4 cs1 = sh4[1 * F4_PER_ROW + t];
    float4 cs2 = sh4[2 * F4_PER_ROW + t];
    float4 cs3 = sh4[3 * F4_PER_ROW + t];

    float4 o0, o1, o2, o3;
    o0.x = fmaf(v0.x, cs0.x, -v0.y * cs0.y);
    o0.y = fmaf(v0.y, cs0.x,  v0.x * cs0.y);
    o0.z = fmaf(v0.z, cs0.z, -v0.w * cs0.w);
    o0.w = fmaf(v0.w, cs0.z,  v0.z * cs0.w);

    o1.x = fmaf(v1.x, cs1.x, -v1.y * cs1.y);
    o1.y = fmaf(v1.y, cs1.x,  v1.x * cs1.y);
    o1.z = fmaf(v1.z, cs1.z, -v1.w * cs1.w);
    o1.w = fmaf(v1.w, cs1.z,  v1.z * cs1.w);

    o2.x = fmaf(v2.x, cs2.x, -v2.y * cs2.y);
    o2.y = fmaf(v2.y, cs2.x,  v2.x * cs2.y);
    o2.z = fmaf(v2.z, cs2.z, -v2.w * cs2.w);
    o2.w = fmaf(v2.w, cs2.z,  v2.z * cs2.w);

    o3.x = fmaf(v3.x, cs3.x, -v3.y * cs3.y);
    o3.y = fmaf(v3.y, cs3.x,  v3.x * cs3.y);
    o3.z = fmaf(v3.z, cs3.z, -v3.w * cs3.w);
    o3.w = fmaf(v3.w, cs3.z,  v3.z * cs3.w);

    __stcs(&out[f0],       o0);
    __stcs(&out[f0 + 256], o1);
    __stcs(&out[f0 + 512], o2);
    __stcs(&out[f0 + 768], o3);
}

extern "C" void kernel_launch(void* const* d_in, const int* in_sizes, int n_in,
                              void* d_out, int out_size) {
    const float4* x = (const float4*)d_in[0];
    const int* grid_sizes = (const int*)d_in[1];
    float4* out = (float4*)d_out;

    int total4 = in_sizes[0] / 4;                    // 8,388,608 float4
    int nblocks = total4 / (ROWS_PER_BLK * 256);     // 8192 blocks
    rope2d_kernel<<<nblocks, 256>>>(x, grid_sizes, out);
}

// round 4
// speedup vs baseline: 1.0872x; 1.0342x over previous
#include <cuda_runtime.h>
#include <math.h>

// RoPE-2D: x[B=32, S=1024, H=16, D=64] fp32, grid_sizes[B,2] int32.
// Combined rotation: rot(i*th) ∘ rot(j*th) == rot((i+j)*th).
// Single kernel, no barrier, no smem: each thread computes its own 4
// {cos,sin} pairs via fast-math MUFU while its streaming loads are in flight.

#define F4_PER_ROW 16        // D=64 floats = 16 float4
#define S_LOG2 10

__global__ void __launch_bounds__(256) rope2d_kernel(const float4* __restrict__ x,
                                                     const int* __restrict__ grid_sizes,
                                                     float4* __restrict__ out) {
    int tid = threadIdx.x;
    int f0 = blockIdx.x * 512 + tid;       // first float4 index
    int f1 = f0 + 256;                     // same t, next s-row

    // ---- issue both streaming loads immediately (MLP=2) ----
    float4 v0 = __ldcs(&x[f0]);
    float4 v1 = __ldcs(&x[f1]);

    // ---- index math + transcendentals overlap the loads ----
    int t = tid & (F4_PER_ROW - 1);                    // pairs k=2t, 2t+1
    unsigned row0 = blockIdx.x * 2;                    // (b,s) row of f0
    unsigned s = row0 & ((1u << S_LOG2) - 1u);
    unsigned b = row0 >> S_LOG2;

    unsigned cols = (unsigned)__ldg(&grid_sizes[2 * b + 1]);
    unsigned i = s / cols;                             // one div for both rows
    unsigned j = s - i * cols;
    int pos0 = (int)(i + j);
    int pos1 = (j + 1u < cols) ? pos0 + 1 : (int)(i + 1u);

    // theta_k = 10000^(-k/32) = exp2(-k * log2(10000)/32)
    const float C = 13.287712379549449f / 32.0f;       // log2(10000)/32
    const float R = 0.7498942093324559f;               // 10000^(-1/32)
    float th0 = exp2f(-(float)(2 * t) * C);
    float th1 = th0 * R;

    float c00, s00, c01, s01, c10, s10, c11, s11;
    __sincosf((float)pos0 * th0, &s00, &c00);
    __sincosf((float)pos0 * th1, &s01, &c01);
    __sincosf((float)pos1 * th0, &s10, &c10);
    __sincosf((float)pos1 * th1, &s11, &c11);

    float4 o0, o1;
    o0.x = fmaf(v0.x, c00, -v0.y * s00);
    o0.y = fmaf(v0.y, c00,  v0.x * s00);
    o0.z = fmaf(v0.z, c01, -v0.w * s01);
    o0.w = fmaf(v0.w, c01,  v0.z * s01);

    o1.x = fmaf(v1.x, c10, -v1.y * s10);
    o1.y = fmaf(v1.y, c10,  v1.x * s10);
    o1.z = fmaf(v1.z, c11, -v1.w * s11);
    o1.w = fmaf(v1.w, c11,  v1.z * s11);

    __stcs(&out[f0], o0);
    __stcs(&out[f1], o1);
}

extern "C" void kernel_launch(void* const* d_in, const int* in_sizes, int n_in,
                              void* d_out, int out_size) {
    const float4* x = (const float4*)d_in[0];
    const int* grid_sizes = (const int*)d_in[1];
    float4* out = (float4*)d_out;

    int total4 = in_sizes[0] / 4;            // 8,388,608 float4
    int nblocks = total4 / 512;              // 16384 blocks, 2 float4/thread
    rope2d_kernel<<<nblocks, 256>>>(x, grid_sizes, out);
}

// round 5
// speedup vs baseline: 1.1008x; 1.0125x over previous
#include <cuda_runtime.h>
#include <math.h>

// RoPE-2D: x[B=32, S=1024, H=16, D=64] fp32, grid_sizes[B,2] int32.
// Combined rotation: rot(i*th) ∘ rot(j*th) == rot((i+j)*th).
// Single kernel, no barrier, no smem. 4 float4/thread (MLP=4), all loads
// front-batched; per-thread fast-math sincos hidden under load latency.

#define F4_PER_ROW 16        // D=64 floats = 16 float4
#define S_LOG2 10

__global__ void __launch_bounds__(256) rope2d_kernel(const float4* __restrict__ x,
                                                     const int* __restrict__ grid_sizes,
                                                     float4* __restrict__ out) {
    int tid = threadIdx.x;
    int f0 = blockIdx.x * 1024 + tid;      // 4 rows (1024 float4) per block

    // ---- issue all 4 streaming loads immediately (MLP=4) ----
    float4 v0 = __ldcs(&x[f0]);
    float4 v1 = __ldcs(&x[f0 + 256]);
    float4 v2 = __ldcs(&x[f0 + 512]);
    float4 v3 = __ldcs(&x[f0 + 768]);

    // ---- positions for the 4 consecutive s-rows (same b, same cols) ----
    unsigned row0 = blockIdx.x * 4;
    unsigned s = row0 & ((1u << S_LOG2) - 1u);
    unsigned b = row0 >> S_LOG2;
    unsigned cols = (unsigned)__ldg(&grid_sizes[2 * b + 1]);

    unsigned i = s / cols;                 // one division for all 4 rows
    unsigned j = s - i * cols;
    int pos0 = (int)(i + j);
    j++; if (j == cols) { j = 0; i++; }
    int pos1 = (int)(i + j);
    j++; if (j == cols) { j = 0; i++; }
    int pos2 = (int)(i + j);
    j++; if (j == cols) { j = 0; i++; }
    int pos3 = (int)(i + j);

    // theta_k = 10000^(-k/32) = exp2(-k * log2(10000)/32)
    int t = tid & (F4_PER_ROW - 1);        // pairs k=2t, 2t+1
    const float C = 13.287712379549449f / 32.0f;   // log2(10000)/32
    const float R = 0.7498942093324559f;           // 10000^(-1/32)
    float th0 = exp2f(-(float)(2 * t) * C);
    float th1 = th0 * R;

    float c00, s00, c01, s01;
    float c10, s10, c11, s11;
    float c20, s20, c21, s21;
    float c30, s30, c31, s31;
    __sincosf((float)pos0 * th0, &s00, &c00);
    __sincosf((float)pos0 * th1, &s01, &c01);
    __sincosf((float)pos1 * th0, &s10, &c10);
    __sincosf((float)pos1 * th1, &s11, &c11);
    __sincosf((float)pos2 * th0, &s20, &c20);
    __sincosf((float)pos2 * th1, &s21, &c21);
    __sincosf((float)pos3 * th0, &s30, &c30);
    __sincosf((float)pos3 * th1, &s31, &c31);

    float4 o0, o1, o2, o3;
    o0.x = fmaf(v0.x, c00, -v0.y * s00);
    o0.y = fmaf(v0.y, c00,  v0.x * s00);
    o0.z = fmaf(v0.z, c01, -v0.w * s01);
    o0.w = fmaf(v0.w, c01,  v0.z * s01);

    o1.x = fmaf(v1.x, c10, -v1.y * s10);
    o1.y = fmaf(v1.y, c10,  v1.x * s10);
    o1.z = fmaf(v1.z, c11, -v1.w * s11);
    o1.w = fmaf(v1.w, c11,  v1.z * s11);

    o2.x = fmaf(v2.x, c20, -v2.y * s20);
    o2.y = fmaf(v2.y, c20,  v2.x * s20);
    o2.z = fmaf(v2.z, c21, -v2.w * s21);
    o2.w = fmaf(v2.w, c21,  v2.z * s21);

    o3.x = fmaf(v3.x, c30, -v3.y * s30);
    o3.y = fmaf(v3.y, c30,  v3.x * s30);
    o3.z = fmaf(v3.z, c31, -v3.w * s31);
    o3.w = fmaf(v3.w, c31,  v3.z * s31);

    __stcs(&out[f0],       o0);
    __stcs(&out[f0 + 256], o1);
    __stcs(&out[f0 + 512], o2);
    __stcs(&out[f0 + 768], o3);
}

extern "C" void kernel_launch(void* const* d_in, const int* in_sizes, int n_in,
                              void* d_out, int out_size) {
    const float4* x = (const float4*)d_in[0];
    const int* grid_sizes = (const int*)d_in[1];
    float4* out = (float4*)d_out;

    int total4 = in_sizes[0] / 4;            // 8,388,608 float4
    int nblocks = total4 / 1024;             // 8192 blocks, 4 float4/thread
    rope2d_kernel<<<nblocks, 256>>>(x, grid_sizes, out);
}